// round 6
// baseline (speedup 1.0000x reference)
#include <cuda_runtime.h>
#include <math.h>

#define B_     64
#define S_EN_  50
#define S_DE_  50
#define H_     32
#define EMB_E_ 64
#define EMB_D_ 32
#define DE_V_  19000
#define VPB    128
#define NBLK   148
#define MAINV  (NBLK * VPB)          // 18944
#define XCOLS  (DE_V_ - MAINV)       // 56 extra columns -> blocks 0..55
#define NTH    256

// ---------------- device-global scratch ----------------
__device__ unsigned long long g_best[S_DE_ * B_ * 2];   // per-step per-row argmax keys (stride 2)
__device__ __align__(16) float g_h[H_ * B_];            // h transposed [k][b]
__device__ unsigned g_fdone[S_DE_][160];                // per-step per-block done flags
__device__ unsigned g_fh[S_DE_ + 1][B_];                // per-step per-row h-ready flags
__device__ unsigned g_cnt = 0, g_gen = 0;               // init barrier only

// ---------------- helpers ----------------
__device__ __forceinline__ unsigned long long pack2(float lo, float hi) {
    unsigned long long r;
    asm("mov.b64 %0, {%1, %2};" : "=l"(r) : "f"(lo), "f"(hi));
    return r;
}
__device__ __forceinline__ float2 unpack2(unsigned long long v) {
    float2 r;
    asm("mov.b64 {%0, %1}, %2;" : "=f"(r.x), "=f"(r.y) : "l"(v));
    return r;
}
__device__ __forceinline__ void fma2(unsigned long long& d, unsigned long long a, unsigned long long b) {
    asm("fma.rn.f32x2 %0, %1, %2, %0;" : "+l"(d) : "l"(a), "l"(b));
}
__device__ __forceinline__ float sigmoidf_(float x) { return 1.0f / (1.0f + expf(-x)); }

__device__ __forceinline__ unsigned long long amax_key(float f, int v) {
    unsigned u = __float_as_uint(f);
    u = (u & 0x80000000u) ? ~u : (u | 0x80000000u);
    return ((unsigned long long)u << 32) | (unsigned long long)(0xFFFFFFFFu - (unsigned)v);
}
__device__ __forceinline__ unsigned ld_acq(const unsigned* p) {
    unsigned v;
    asm volatile("ld.acquire.gpu.global.u32 %0, [%1];" : "=r"(v) : "l"(p) : "memory");
    return v;
}
__device__ __forceinline__ void st_rel(unsigned* p, unsigned v) {
    asm volatile("st.release.gpu.global.u32 [%0], %1;" :: "l"(p), "r"(v) : "memory");
}
__device__ __forceinline__ void red_max64(unsigned long long* p, unsigned long long v) {
    asm volatile("red.relaxed.gpu.global.max.u64 [%0], %1;" :: "l"(p), "l"(v) : "memory");
}

// warp0-wide poll: wait until flags[0..n-1] all nonzero (acquire)
__device__ __forceinline__ void poll_all(const unsigned* base, int n) {
    const int lane = threadIdx.x & 31;
    for (;;) {
        unsigned ok = 1u;
        for (int j = lane; j < n; j += 32) ok &= (ld_acq(base + j) != 0u);
        if (__all_sync(0xffffffffu, ok)) break;
    }
}

// one-time init barrier (replay-safe)
__device__ __forceinline__ void grid_barrier() {
    __threadfence();
    __syncthreads();
    if (threadIdx.x == 0) {
        unsigned my = *(volatile unsigned*)&g_gen;
        __threadfence();
        if (atomicAdd(&g_cnt, 1u) == NBLK - 1) {
            g_cnt = 0;
            __threadfence();
            atomicAdd(&g_gen, 1u);
        } else {
            while (*(volatile unsigned*)&g_gen == my) { __nanosleep(32); }
        }
    }
    __syncthreads();
}

__global__ void __launch_bounds__(NTH, 1)
seq2seq_kernel(const int* __restrict__ en_batch, const int* __restrict__ en_lens,
               const int* __restrict__ de_batch,
               const float* __restrict__ en_emb,
               const float* __restrict__ eWih, const float* __restrict__ eWhh,
               const float* __restrict__ ebih, const float* __restrict__ ebhh,
               const float* __restrict__ de_emb,
               const float* __restrict__ dWih, const float* __restrict__ dWhh,
               const float* __restrict__ dbih, const float* __restrict__ dbhh,
               const float* __restrict__ fcW, const float* __restrict__ fcb,
               float* __restrict__ out)
{
    __shared__ __align__(16) float sW[H_][VPB];              // fc_W tile [k][v-local]
    __shared__ unsigned long long sWb2[VPB / 2];             // fc_b pairs
    __shared__ __align__(16) unsigned long long sH2[H_][B_]; // (h,h) packed [k][b]
    __shared__ unsigned long long sBest[B_];
    __shared__ float sPart[2][4 * H_];
    __shared__ float sBias[4 * H_];
    __shared__ float sX[EMB_E_];
    __shared__ float sWx[H_];                                // extra-column weights
    __shared__ float s_h[H_], s_c[H_];
    __shared__ int   sToks[S_EN_];
    __shared__ int   s_tok;

    const int tid = threadIdx.x;
    const int bk  = blockIdx.x;
    const int v0  = bk * VPB;
    const int jg  = tid & 127;      // gate index
    const int hf  = tid >> 7;       // half selector
    const bool has_x = (bk < XCOLS);
    const int  xcol  = MAINV + bk;

    // ---------- phase 0: zero out[:,0,:], zero sync state ----------
    for (int i = tid; i < B_ * VPB; i += NTH) {
        int b = i / VPB, v = i % VPB;
        out[(size_t)(b * S_DE_) * DE_V_ + v0 + v] = 0.0f;
    }
    if (has_x && tid < B_) out[(size_t)(tid * S_DE_) * DE_V_ + xcol] = 0.0f;
    {
        int gt = bk * NTH + tid;
        if (gt < S_DE_ * B_ * 2) g_best[gt] = 0ull;
        if (gt < S_DE_ * 160) (&g_fdone[0][0])[gt] = 0u;
        if (gt < (S_DE_ + 1) * B_) (&g_fh[0][0])[gt] = 0u;
    }

    // ---------- fc tile into smem ----------
    for (int i = tid; i < H_ * VPB; i += NTH) {
        int v = i >> 5, k = i & 31;
        sW[k][v] = fcW[(size_t)(v0 + v) * H_ + k];
    }
    for (int i = tid; i < VPB / 2; i += NTH)
        sWb2[i] = pack2(fcb[v0 + 2 * i], fcb[v0 + 2 * i + 1]);
    float bxv = 0.0f;
    if (has_x) {
        if (tid < H_) sWx[tid] = fcW[(size_t)xcol * H_ + tid];
        bxv = fcb[xcol];
    }

    grid_barrier();     // zeroed flags visible chip-wide before any set/poll

    float wreg[48];

    // ---------- encoder + first decoder LSTM: blocks 0..63 ----------
    if (bk < B_) {
        #pragma unroll
        for (int k = 0; k < 32; k++) wreg[k] = eWih[jg * EMB_E_ + hf * 32 + k];
        #pragma unroll
        for (int k = 0; k < 16; k++) wreg[32 + k] = eWhh[jg * H_ + hf * 16 + k];
        if (tid < 4 * H_) sBias[tid] = ebih[tid] + ebhh[tid];
        if (tid < H_) { s_h[tid] = 0.0f; s_c[tid] = 0.0f; }
        if (tid < S_EN_) sToks[tid] = en_batch[bk * S_EN_ + tid];
        __syncthreads();

        const int len = en_lens[bk];
        float xr = 0.0f;
        if (tid < EMB_E_ && len > 0) xr = en_emb[(size_t)sToks[0] * EMB_E_ + tid];
        for (int t = 0; t < len; t++) {
            if (tid < EMB_E_) sX[tid] = xr;
            __syncthreads();
            if (tid < EMB_E_ && t + 1 < len)                   // prefetch next emb
                xr = en_emb[(size_t)sToks[t + 1] * EMB_E_ + tid];
            {
                float p = 0.0f;
                #pragma unroll
                for (int k = 0; k < 32; k++) p += sX[hf * 32 + k] * wreg[k];
                #pragma unroll
                for (int k = 0; k < 16; k++) p += s_h[hf * 16 + k] * wreg[32 + k];
                sPart[hf][jg] = p;
            }
            __syncthreads();
            if (tid < H_) {
                float gi = sPart[0][tid]          + sPart[1][tid]          + sBias[tid];
                float gf = sPart[0][H_ + tid]     + sPart[1][H_ + tid]     + sBias[H_ + tid];
                float gg = sPart[0][2 * H_ + tid] + sPart[1][2 * H_ + tid] + sBias[2 * H_ + tid];
                float go = sPart[0][3 * H_ + tid] + sPart[1][3 * H_ + tid] + sBias[3 * H_ + tid];
                float ig = sigmoidf_(gi), fg = sigmoidf_(gf), og = sigmoidf_(go);
                float c  = fg * s_c[tid] + ig * tanhf(gg);
                s_c[tid] = c;
                s_h[tid] = og * tanhf(c);
            }
            __syncthreads();
        }

        // decoder weights: hf0 threads own Wih row, hf1 threads own Whh row
        #pragma unroll
        for (int k = 0; k < 32; k++)
            wreg[k] = hf ? dWhh[jg * H_ + k] : dWih[jg * EMB_D_ + k];
        if (tid < 4 * H_) sBias[tid] = dbih[tid] + dbhh[tid];
        __syncthreads();

        // first decoder step
        {
            int tok = de_batch[bk * S_DE_];
            if (tid < EMB_D_) sX[tid] = de_emb[(size_t)tok * EMB_D_ + tid];
            __syncthreads();
            {
                const float* src = hf ? s_h : sX;
                float p = 0.0f;
                #pragma unroll
                for (int k = 0; k < 32; k++) p += src[k] * wreg[k];
                sPart[hf][jg] = p;
            }
            __syncthreads();
            if (tid < H_) {
                float gi = sPart[0][tid]          + sPart[1][tid]          + sBias[tid];
                float gf = sPart[0][H_ + tid]     + sPart[1][H_ + tid]     + sBias[H_ + tid];
                float gg = sPart[0][2 * H_ + tid] + sPart[1][2 * H_ + tid] + sBias[2 * H_ + tid];
                float go = sPart[0][3 * H_ + tid] + sPart[1][3 * H_ + tid] + sBias[3 * H_ + tid];
                float ig = sigmoidf_(gi), fg = sigmoidf_(gf), og = sigmoidf_(go);
                float c  = fg * s_c[tid] + ig * tanhf(gg);
                s_c[tid] = c;
                float h  = og * tanhf(c);
                s_h[tid] = h;
                __stcg(&g_h[tid * B_ + bk], h);
            }
            __syncthreads();
            if (tid == 0) st_rel(&g_fh[1][bk], 1u);
            if (hf == 1) {          // precompute Whh·h for next step
                float p = 0.0f;
                #pragma unroll
                for (int k = 0; k < 32; k++) p += s_h[k] * wreg[k];
                sPart[1][jg] = p;
            }
        }
    }

    const int bq  = tid & 15;       // b-lane
    const int vq  = tid >> 4;       // v-octet
    const int vl0 = vq * 8;

    for (int s = 1; s < S_DE_; s++) {
        // ---------- wait for h_s, broadcast to smem ----------
        if (tid < 32) poll_all(&g_fh[s][0], B_);
        __syncthreads();
        {
            const float4* src = (const float4*)g_h;
            unsigned long long* dst = &sH2[0][0];
            for (int i = tid; i < H_ * B_ / 4; i += NTH) {
                float4 v = __ldcg(&src[i]);
                dst[4 * i + 0] = pack2(v.x, v.x);
                dst[4 * i + 1] = pack2(v.y, v.y);
                dst[4 * i + 2] = pack2(v.z, v.z);
                dst[4 * i + 3] = pack2(v.w, v.w);
            }
            if (tid < B_) sBest[tid] = 0ull;
        }
        __syncthreads();

        // ---------- logits tile ----------
        unsigned long long acc[4][4];
        #pragma unroll
        for (int i = 0; i < 4; i++)
            #pragma unroll
            for (int j = 0; j < 4; j++) acc[i][j] = sWb2[vq * 4 + j];

        #pragma unroll 8
        for (int k = 0; k < H_; k++) {
            const unsigned long long* w64 = (const unsigned long long*)&sW[k][0];
            unsigned long long w0 = w64[vq * 4 + 0];
            unsigned long long w1 = w64[vq * 4 + 1];
            unsigned long long w2 = w64[vq * 4 + 2];
            unsigned long long w3 = w64[vq * 4 + 3];
            #pragma unroll
            for (int i = 0; i < 4; i++) {
                unsigned long long hh = sH2[k][bq + 16 * i];
                fma2(acc[i][0], hh, w0);
                fma2(acc[i][1], hh, w1);
                fma2(acc[i][2], hh, w2);
                fma2(acc[i][3], hh, w3);
            }
        }

        const bool last = (s == S_DE_ - 1);

        // ---------- per-block argmax (skip on last step: token unused) ----------
        if (!last) {
            #pragma unroll
            for (int i = 0; i < 4; i++) {
                const int b = bq + 16 * i;
                float2 p0 = unpack2(acc[i][0]);
                float2 p1 = unpack2(acc[i][1]);
                float2 p2 = unpack2(acc[i][2]);
                float2 p3 = unpack2(acc[i][3]);
                const int vb = v0 + vl0;
                unsigned long long best = amax_key(p0.x, vb);
                unsigned long long k2;
                k2 = amax_key(p0.y, vb + 1); if (k2 > best) best = k2;
                k2 = amax_key(p1.x, vb + 2); if (k2 > best) best = k2;
                k2 = amax_key(p1.y, vb + 3); if (k2 > best) best = k2;
                k2 = amax_key(p2.x, vb + 4); if (k2 > best) best = k2;
                k2 = amax_key(p2.y, vb + 5); if (k2 > best) best = k2;
                k2 = amax_key(p3.x, vb + 6); if (k2 > best) best = k2;
                k2 = amax_key(p3.y, vb + 7); if (k2 > best) best = k2;
                atomicMax(&sBest[b], best);
            }
        }

        // ---------- extra column (blocks 0..55) ----------
        float xdot = 0.0f;
        if (has_x && tid < B_) {
            const float* sH2f = (const float*)&sH2[0][0];
            float p = bxv;
            #pragma unroll
            for (int k = 0; k < H_; k++) p += sH2f[(k * B_ + tid) * 2] * sWx[k];
            xdot = p;
            if (!last) atomicMax(&sBest[tid], amax_key(p, xcol));
        }
        __syncthreads();

        if (!last) {
            if (tid < B_) red_max64(&g_best[(size_t)(s * B_ + tid) * 2], sBest[tid]);
            __syncthreads();
            if (tid == 0) st_rel(&g_fdone[s][bk], 1u);
        }

        // ---------- bulk logits stores: off the critical path ----------
        #pragma unroll
        for (int i = 0; i < 4; i++) {
            const int b = bq + 16 * i;
            float2 p0 = unpack2(acc[i][0]);
            float2 p1 = unpack2(acc[i][1]);
            float2 p2 = unpack2(acc[i][2]);
            float2 p3 = unpack2(acc[i][3]);
            float4* orow = (float4*)(out + ((size_t)b * S_DE_ + s) * DE_V_ + v0 + vl0);
            __stcs(&orow[0], make_float4(p0.x, p0.y, p1.x, p1.y));
            __stcs(&orow[1], make_float4(p2.x, p2.y, p3.x, p3.y));
        }
        if (has_x && tid < B_)
            __stcs(&out[((size_t)tid * S_DE_ + s) * DE_V_ + xcol], xdot);

        // ---------- LSTM: produce h for step s+1 (blocks 0..63) ----------
        if (!last && bk < B_) {
            if (tid < 32) {
                poll_all(&g_fdone[s][0], NBLK);
                if (tid == 0) {
                    unsigned long long key = __ldcg(&g_best[(size_t)(s * B_ + bk) * 2]);
                    s_tok = (int)(0xFFFFFFFFu - (unsigned)(key & 0xFFFFFFFFull));
                }
                __syncwarp();
                if (tid < EMB_D_) sX[tid] = de_emb[(size_t)s_tok * EMB_D_ + tid];
            }
            __syncthreads();
            if (hf == 0) {                      // x-part only; h-part was precomputed
                float p = 0.0f;
                #pragma unroll
                for (int k = 0; k < 32; k++) p += sX[k] * wreg[k];
                sPart[0][jg] = p;
            }
            __syncthreads();
            if (tid < H_) {
                float gi = sPart[0][tid]          + sPart[1][tid]          + sBias[tid];
                float gf = sPart[0][H_ + tid]     + sPart[1][H_ + tid]     + sBias[H_ + tid];
                float gg = sPart[0][2 * H_ + tid] + sPart[1][2 * H_ + tid] + sBias[2 * H_ + tid];
                float go = sPart[0][3 * H_ + tid] + sPart[1][3 * H_ + tid] + sBias[3 * H_ + tid];
                float ig = sigmoidf_(gi), fg = sigmoidf_(gf), og = sigmoidf_(go);
                float c  = fg * s_c[tid] + ig * tanhf(gg);
                s_c[tid] = c;
                float h  = og * tanhf(c);
                s_h[tid] = h;
                __stcg(&g_h[tid * B_ + bk], h);
            }
            __syncthreads();
            if (tid == 0) st_rel(&g_fh[s + 1][bk], 1u);
            if (hf == 1) {                      // precompute Whh·h for next step
                float p = 0.0f;
                #pragma unroll
                for (int k = 0; k < 32; k++) p += s_h[k] * wreg[k];
                sPart[1][jg] = p;
            }
        }
    }
}

extern "C" void kernel_launch(void* const* d_in, const int* in_sizes, int n_in,
                              void* d_out, int out_size) {
    const int*   en_batch = (const int*)d_in[0];
    const int*   en_lens  = (const int*)d_in[1];
    const int*   de_batch = (const int*)d_in[2];
    const float* en_emb   = (const float*)d_in[3];
    const float* eWih     = (const float*)d_in[4];
    const float* eWhh     = (const float*)d_in[5];
    const float* ebih     = (const float*)d_in[6];
    const float* ebhh     = (const float*)d_in[7];
    const float* de_emb   = (const float*)d_in[8];
    const float* dWih     = (const float*)d_in[9];
    const float* dWhh     = (const float*)d_in[10];
    const float* dbih     = (const float*)d_in[11];
    const float* dbhh     = (const float*)d_in[12];
    const float* fcW      = (const float*)d_in[13];
    const float* fcb      = (const float*)d_in[14];

    seq2seq_kernel<<<NBLK, NTH>>>(en_batch, en_lens, de_batch, en_emb,
                                  eWih, eWhh, ebih, ebhh,
                                  de_emb, dWih, dWhh, dbih, dbhh,
                                  fcW, fcb, (float*)d_out);
}

// round 9
// speedup vs baseline: 1.3485x; 1.3485x over previous
#include <cuda_runtime.h>
#include <math.h>

#define B_     64
#define S_EN_  50
#define S_DE_  50
#define H_     32
#define EMB_E_ 64
#define EMB_D_ 32
#define DE_V_  19000
#define VPB    128
#define NBLK   148
#define MAINV  (NBLK * VPB)          // 18944
#define XCOLS  (DE_V_ - MAINV)       // 56 extra columns -> blocks 0..55
#define NTH    256

// ---------------- device-global scratch ----------------
__device__ unsigned long long g_best[S_DE_ * B_ * 2];   // per-step per-row argmax keys (stride 2)
__device__ __align__(16) float g_h[H_ * B_];            // h transposed [k][b]
__device__ unsigned g_hcnt[S_DE_ + 1], g_hready[S_DE_ + 1];   // LSTM arrivals / ready
__device__ unsigned g_dcnt[S_DE_],     g_dready[S_DE_];       // GEMM arrivals / ready
__device__ unsigned g_cnt = 0, g_gen = 0;               // init barrier only

// ---------------- helpers ----------------
__device__ __forceinline__ unsigned long long pack2(float lo, float hi) {
    unsigned long long r;
    asm("mov.b64 %0, {%1, %2};" : "=l"(r) : "f"(lo), "f"(hi));
    return r;
}
__device__ __forceinline__ float2 unpack2(unsigned long long v) {
    float2 r;
    asm("mov.b64 {%0, %1}, %2;" : "=f"(r.x), "=f"(r.y) : "l"(v));
    return r;
}
__device__ __forceinline__ void fma2(unsigned long long& d, unsigned long long a, unsigned long long b) {
    asm("fma.rn.f32x2 %0, %1, %2, %0;" : "+l"(d) : "l"(a), "l"(b));
}
__device__ __forceinline__ float sigmoidf_(float x) { return 1.0f / (1.0f + expf(-x)); }

// larger key == (bigger value, then smaller index) -> matches jnp.argmax
__device__ __forceinline__ unsigned long long amax_key(float f, int v) {
    unsigned u = __float_as_uint(f);
    u = (u & 0x80000000u) ? ~u : (u | 0x80000000u);
    return ((unsigned long long)u << 32) | (unsigned long long)(0xFFFFFFFFu - (unsigned)v);
}
__device__ __forceinline__ unsigned ld_acq(const unsigned* p) {
    unsigned v;
    asm volatile("ld.acquire.gpu.global.u32 %0, [%1];" : "=r"(v) : "l"(p) : "memory");
    return v;
}
__device__ __forceinline__ void st_rel(unsigned* p, unsigned v) {
    asm volatile("st.release.gpu.global.u32 [%0], %1;" :: "l"(p), "r"(v) : "memory");
}
__device__ __forceinline__ void red_max64(unsigned long long* p, unsigned long long v) {
    asm volatile("red.relaxed.gpu.global.max.u64 [%0], %1;" :: "l"(p), "l"(v) : "memory");
}
__device__ __forceinline__ void spin_until(const unsigned* p) {
    while (ld_acq(p) == 0u) {}
}

// one-time init barrier (replay-safe)
__device__ __forceinline__ void grid_barrier() {
    __threadfence();
    __syncthreads();
    if (threadIdx.x == 0) {
        unsigned my = *(volatile unsigned*)&g_gen;
        __threadfence();
        if (atomicAdd(&g_cnt, 1u) == NBLK - 1) {
            g_cnt = 0;
            __threadfence();
            atomicAdd(&g_gen, 1u);
        } else {
            while (*(volatile unsigned*)&g_gen == my) { __nanosleep(32); }
        }
    }
    __syncthreads();
}

__global__ void __launch_bounds__(NTH, 1)
seq2seq_kernel(const int* __restrict__ en_batch, const int* __restrict__ en_lens,
               const int* __restrict__ de_batch,
               const float* __restrict__ en_emb,
               const float* __restrict__ eWih, const float* __restrict__ eWhh,
               const float* __restrict__ ebih, const float* __restrict__ ebhh,
               const float* __restrict__ de_emb,
               const float* __restrict__ dWih, const float* __restrict__ dWhh,
               const float* __restrict__ dbih, const float* __restrict__ dbhh,
               const float* __restrict__ fcW, const float* __restrict__ fcb,
               float* __restrict__ out)
{
    __shared__ __align__(16) float sW[H_][VPB];              // fc_W tile [k][v-local]
    __shared__ unsigned long long sWb2[VPB / 2];             // fc_b pairs
    __shared__ __align__(16) unsigned long long sH2[H_][B_]; // (h,h) packed [k][b]
    __shared__ unsigned long long sRedW[8][B_];              // per-warp per-row argmax partials
    __shared__ float sPart[2][4 * H_];
    __shared__ float sBias[4 * H_];
    __shared__ float sX[EMB_E_];
    __shared__ float sWx[H_];                                // extra-column weights
    __shared__ float s_h[H_], s_c[H_];
    __shared__ int   sToks[S_EN_];
    __shared__ int   s_tok;

    const int tid  = threadIdx.x;
    const int bk   = blockIdx.x;
    const int v0   = bk * VPB;
    const int jg   = tid & 127;     // gate index
    const int hf   = tid >> 7;      // half selector
    const int wid  = tid >> 5;
    const int lane = tid & 31;
    const bool has_x = (bk < XCOLS);
    const int  xcol  = MAINV + bk;

    // ---------- phase 0: zero out[:,0,:], zero sync state ----------
    for (int i = tid; i < B_ * VPB; i += NTH) {
        int b = i / VPB, v = i % VPB;
        out[(size_t)(b * S_DE_) * DE_V_ + v0 + v] = 0.0f;
    }
    if (has_x && tid < B_) out[(size_t)(tid * S_DE_) * DE_V_ + xcol] = 0.0f;
    {
        int gt = bk * NTH + tid;
        if (gt < S_DE_ * B_ * 2) g_best[gt] = 0ull;
        if (gt < S_DE_ + 1) { g_hcnt[gt] = 0u; g_hready[gt] = 0u; }
        if (gt < S_DE_)     { g_dcnt[gt] = 0u; g_dready[gt] = 0u; }
    }

    // ---------- fc tile into smem ----------
    for (int i = tid; i < H_ * VPB; i += NTH) {
        int v = i >> 5, k = i & 31;
        sW[k][v] = fcW[(size_t)(v0 + v) * H_ + k];
    }
    for (int i = tid; i < VPB / 2; i += NTH)
        sWb2[i] = pack2(fcb[v0 + 2 * i], fcb[v0 + 2 * i + 1]);
    float bxv = 0.0f;
    if (has_x) {
        if (tid < H_) sWx[tid] = fcW[(size_t)xcol * H_ + tid];
        bxv = fcb[xcol];
    }

    grid_barrier();     // zeroed flags visible chip-wide before any set/poll

    float wreg[48];

    // ---------- encoder + first decoder LSTM: blocks 0..63 ----------
    if (bk < B_) {
        #pragma unroll
        for (int k = 0; k < 32; k++) wreg[k] = eWih[jg * EMB_E_ + hf * 32 + k];
        #pragma unroll
        for (int k = 0; k < 16; k++) wreg[32 + k] = eWhh[jg * H_ + hf * 16 + k];
        if (tid < 4 * H_) sBias[tid] = ebih[tid] + ebhh[tid];
        if (tid < H_) { s_h[tid] = 0.0f; s_c[tid] = 0.0f; }
        if (tid < S_EN_) sToks[tid] = en_batch[bk * S_EN_ + tid];
        __syncthreads();

        const int len = en_lens[bk];
        float xr = 0.0f;
        if (tid < EMB_E_ && len > 0) xr = en_emb[(size_t)sToks[0] * EMB_E_ + tid];
        for (int t = 0; t < len; t++) {
            if (tid < EMB_E_) sX[tid] = xr;
            __syncthreads();
            if (tid < EMB_E_ && t + 1 < len)                   // prefetch next emb
                xr = en_emb[(size_t)sToks[t + 1] * EMB_E_ + tid];
            {
                float p = 0.0f;
                #pragma unroll
                for (int k = 0; k < 32; k++) p += sX[hf * 32 + k] * wreg[k];
                #pragma unroll
                for (int k = 0; k < 16; k++) p += s_h[hf * 16 + k] * wreg[32 + k];
                sPart[hf][jg] = p;
            }
            __syncthreads();
            if (tid < H_) {
                float gi = sPart[0][tid]          + sPart[1][tid]          + sBias[tid];
                float gf = sPart[0][H_ + tid]     + sPart[1][H_ + tid]     + sBias[H_ + tid];
                float gg = sPart[0][2 * H_ + tid] + sPart[1][2 * H_ + tid] + sBias[2 * H_ + tid];
                float go = sPart[0][3 * H_ + tid] + sPart[1][3 * H_ + tid] + sBias[3 * H_ + tid];
                float ig = sigmoidf_(gi), fg = sigmoidf_(gf), og = sigmoidf_(go);
                float c  = fg * s_c[tid] + ig * tanhf(gg);
                s_c[tid] = c;
                s_h[tid] = og * tanhf(c);
            }
            __syncthreads();
        }

        // decoder weights: hf0 threads own Wih row, hf1 threads own Whh row
        #pragma unroll
        for (int k = 0; k < 32; k++)
            wreg[k] = hf ? dWhh[jg * H_ + k] : dWih[jg * EMB_D_ + k];
        if (tid < 4 * H_) sBias[tid] = dbih[tid] + dbhh[tid];
        __syncthreads();

        // first decoder step
        {
            int tok = de_batch[bk * S_DE_];
            if (tid < EMB_D_) sX[tid] = de_emb[(size_t)tok * EMB_D_ + tid];
            __syncthreads();
            {
                const float* src = hf ? s_h : sX;
                float p = 0.0f;
                #pragma unroll
                for (int k = 0; k < 32; k++) p += src[k] * wreg[k];
                sPart[hf][jg] = p;
            }
            __syncthreads();
            if (tid < H_) {
                float gi = sPart[0][tid]          + sPart[1][tid]          + sBias[tid];
                float gf = sPart[0][H_ + tid]     + sPart[1][H_ + tid]     + sBias[H_ + tid];
                float gg = sPart[0][2 * H_ + tid] + sPart[1][2 * H_ + tid] + sBias[2 * H_ + tid];
                float go = sPart[0][3 * H_ + tid] + sPart[1][3 * H_ + tid] + sBias[3 * H_ + tid];
                float ig = sigmoidf_(gi), fg = sigmoidf_(gf), og = sigmoidf_(go);
                float c  = fg * s_c[tid] + ig * tanhf(gg);
                s_c[tid] = c;
                float h  = og * tanhf(c);
                s_h[tid] = h;
                __stcg(&g_h[tid * B_ + bk], h);
            }
            __syncwarp();
            if (tid == 0) {
                __threadfence();
                if (atomicAdd(&g_hcnt[1], 1u) == B_ - 1) st_rel(&g_hready[1], 1u);
            }
            __syncthreads();
            if (hf == 1) {          // precompute Whh·h for next step
                float p = 0.0f;
                #pragma unroll
                for (int k = 0; k < 32; k++) p += s_h[k] * wreg[k];
                sPart[1][jg] = p;
            }
        }
    }

    const int bq  = tid & 15;       // b-lane
    const int vq  = tid >> 4;       // v-octet
    const int vl0 = vq * 8;

    for (int s = 1; s < S_DE_; s++) {
        // ---------- wait for h_s, broadcast to smem ----------
        if (tid == 0) spin_until(&g_hready[s]);
        __syncthreads();
        {
            const float4* src = (const float4*)g_h;
            unsigned long long* dst = &sH2[0][0];
            for (int i = tid; i < H_ * B_ / 4; i += NTH) {
                float4 v = __ldcg(&src[i]);
                dst[4 * i + 0] = pack2(v.x, v.x);
                dst[4 * i + 1] = pack2(v.y, v.y);
                dst[4 * i + 2] = pack2(v.z, v.z);
                dst[4 * i + 3] = pack2(v.w, v.w);
            }
        }
        __syncthreads();

        // ---------- logits tile ----------
        unsigned long long acc[4][4];
        #pragma unroll
        for (int i = 0; i < 4; i++)
            #pragma unroll
            for (int j = 0; j < 4; j++) acc[i][j] = sWb2[vq * 4 + j];

        #pragma unroll 8
        for (int k = 0; k < H_; k++) {
            const unsigned long long* w64 = (const unsigned long long*)&sW[k][0];
            unsigned long long w0 = w64[vq * 4 + 0];
            unsigned long long w1 = w64[vq * 4 + 1];
            unsigned long long w2 = w64[vq * 4 + 2];
            unsigned long long w3 = w64[vq * 4 + 3];
            #pragma unroll
            for (int i = 0; i < 4; i++) {
                unsigned long long hh = sH2[k][bq + 16 * i];
                fma2(acc[i][0], hh, w0);
                fma2(acc[i][1], hh, w1);
                fma2(acc[i][2], hh, w2);
                fma2(acc[i][3], hh, w3);
            }
        }

        const bool last = (s == S_DE_ - 1);

        // ---------- extra column (blocks 0..55), thread tid == row ----------
        float xdot = 0.0f;
        if (has_x && tid < B_) {
            const float* sH2f = (const float*)&sH2[0][0];
            float p = bxv;
            #pragma unroll
            for (int k = 0; k < H_; k++) p += sH2f[(k * B_ + tid) * 2] * sWx[k];
            xdot = p;
        }

        // ---------- argmax: registers -> shfl -> smem -> 64-thread reduce ----------
        if (!last) {
            const int vb = v0 + vl0;
            unsigned long long kr[4];
            #pragma unroll
            for (int i = 0; i < 4; i++) {
                float2 p0 = unpack2(acc[i][0]);
                float2 p1 = unpack2(acc[i][1]);
                float2 p2 = unpack2(acc[i][2]);
                float2 p3 = unpack2(acc[i][3]);
                unsigned long long best = amax_key(p0.x, vb);
                unsigned long long k2;
                k2 = amax_key(p0.y, vb + 1); if (k2 > best) best = k2;
                k2 = amax_key(p1.x, vb + 2); if (k2 > best) best = k2;
                k2 = amax_key(p1.y, vb + 3); if (k2 > best) best = k2;
                k2 = amax_key(p2.x, vb + 4); if (k2 > best) best = k2;
                k2 = amax_key(p2.y, vb + 5); if (k2 > best) best = k2;
                k2 = amax_key(p3.x, vb + 6); if (k2 > best) best = k2;
                k2 = amax_key(p3.y, vb + 7); if (k2 > best) best = k2;
                kr[i] = best;
            }
            #pragma unroll
            for (int i = 0; i < 4; i++) {
                unsigned long long o = __shfl_xor_sync(0xffffffffu, kr[i], 16);
                if (o > kr[i]) kr[i] = o;
            }
            if (lane < 16) {
                #pragma unroll
                for (int i = 0; i < 4; i++) sRedW[wid][bq + 16 * i] = kr[i];
            }
            __syncthreads();
            if (tid < B_) {
                unsigned long long best = sRedW[0][tid];
                #pragma unroll
                for (int w = 1; w < 8; w++) { unsigned long long o = sRedW[w][tid]; if (o > best) best = o; }
                if (has_x) { unsigned long long o = amax_key(xdot, xcol); if (o > best) best = o; }
                red_max64(&g_best[(size_t)(s * B_ + tid) * 2], best);
            }
            __syncthreads();
            if (tid == 0) {
                __threadfence();
                if (atomicAdd(&g_dcnt[s], 1u) == NBLK - 1) st_rel(&g_dready[s], 1u);
            }
        }

        // ---------- bulk logits stores: off the critical path ----------
        #pragma unroll
        for (int i = 0; i < 4; i++) {
            const int b = bq + 16 * i;
            float2 p0 = unpack2(acc[i][0]);
            float2 p1 = unpack2(acc[i][1]);
            float2 p2 = unpack2(acc[i][2]);
            float2 p3 = unpack2(acc[i][3]);
            float4* orow = (float4*)(out + ((size_t)b * S_DE_ + s) * DE_V_ + v0 + vl0);
            __stcs(&orow[0], make_float4(p0.x, p0.y, p1.x, p1.y));
            __stcs(&orow[1], make_float4(p2.x, p2.y, p3.x, p3.y));
        }
        if (has_x && tid < B_)
            __stcs(&out[((size_t)tid * S_DE_ + s) * DE_V_ + xcol], xdot);

        // ---------- LSTM: produce h for step s+1 (blocks 0..63) ----------
        if (!last && bk < B_) {
            if (tid == 0) {
                spin_until(&g_dready[s]);
                unsigned long long key = __ldcg(&g_best[(size_t)(s * B_ + bk) * 2]);
                s_tok = (int)(0xFFFFFFFFu - (unsigned)(key & 0xFFFFFFFFull));
            }
            if (tid < 32) {
                __syncwarp();
                if (tid < EMB_D_) sX[tid] = de_emb[(size_t)s_tok * EMB_D_ + tid];
            }
            __syncthreads();
            if (hf == 0) {                      // x-part only; h-part precomputed
                float p = 0.0f;
                #pragma unroll
                for (int k = 0; k < 32; k++) p += sX[k] * wreg[k];
                sPart[0][jg] = p;
            }
            __syncthreads();
            if (tid < H_) {
                float gi = sPart[0][tid]          + sPart[1][tid]          + sBias[tid];
                float gf = sPart[0][H_ + tid]     + sPart[1][H_ + tid]     + sBias[H_ + tid];
                float gg = sPart[0][2 * H_ + tid] + sPart[1][2 * H_ + tid] + sBias[2 * H_ + tid];
                float go = sPart[0][3 * H_ + tid] + sPart[1][3 * H_ + tid] + sBias[3 * H_ + tid];
                float ig = sigmoidf_(gi), fg = sigmoidf_(gf), og = sigmoidf_(go);
                float c  = fg * s_c[tid] + ig * tanhf(gg);
                s_c[tid] = c;
                float h  = og * tanhf(c);
                s_h[tid] = h;
                __stcg(&g_h[tid * B_ + bk], h);
            }
            __syncwarp();
            if (tid == 0) {
                __threadfence();
                if (atomicAdd(&g_hcnt[s + 1], 1u) == B_ - 1) st_rel(&g_hready[s + 1], 1u);
            }
            __syncthreads();
            if (hf == 1) {                      // precompute Whh·h for next step
                float p = 0.0f;
                #pragma unroll
                for (int k = 0; k < 32; k++) p += s_h[k] * wreg[k];
                sPart[1][jg] = p;
            }
        }
    }
}

extern "C" void kernel_launch(void* const* d_in, const int* in_sizes, int n_in,
                              void* d_out, int out_size) {
    const int*   en_batch = (const int*)d_in[0];
    const int*   en_lens  = (const int*)d_in[1];
    const int*   de_batch = (const int*)d_in[2];
    const float* en_emb   = (const float*)d_in[3];
    const float* eWih     = (const float*)d_in[4];
    const float* eWhh     = (const float*)d_in[5];
    const float* ebih     = (const float*)d_in[6];
    const float* ebhh     = (const float*)d_in[7];
    const float* de_emb   = (const float*)d_in[8];
    const float* dWih     = (const float*)d_in[9];
    const float* dWhh     = (const float*)d_in[10];
    const float* dbih     = (const float*)d_in[11];
    const float* dbhh     = (const float*)d_in[12];
    const float* fcW      = (const float*)d_in[13];
    const float* fcb      = (const float*)d_in[14];

    seq2seq_kernel<<<NBLK, NTH>>>(en_batch, en_lens, de_batch, en_emb,
                                  eWih, eWhh, ebih, ebhh,
                                  de_emb, dWih, dWhh, dbih, dbhh,
                                  fcW, fcb, (float*)d_out);
}